// round 15
// baseline (speedup 1.0000x reference)
#include <cuda_runtime.h>
#include <cuda_fp16.h>
#include <math.h>

// Problem constants
#define B_  4
#define L_  2048
#define D_  1024
#define H_  16
#define HD_ 64
#define M_  (B_ * L_)          // 8192
#define QKV_N (3 * D_)         // 3072

typedef __half f16;

// ---------------------------------------------------------------------------
// Scratch (device globals)
// ---------------------------------------------------------------------------
__device__ float g_qkv[M_ * QKV_N];                    // fp32 qkv rows
__device__ f16 g_xh[M_ * D_],     g_xl[M_ * D_];       // x hi/lo
__device__ f16 g_wqh[QKV_N * D_], g_wql[QKV_N * D_];   // W_qkv hi/lo
__device__ f16 g_wph[D_ * D_],    g_wpl[D_ * D_];      // W_proj hi/lo
__device__ f16 g_qh[M_ * D_], g_ql[M_ * D_];           // Q [b,h,l,hd] hi/lo
__device__ f16 g_kh[M_ * D_], g_kl[M_ * D_];           // K
__device__ f16 g_vh[M_ * D_], g_vl[M_ * D_];           // V
__device__ f16 g_aoh[M_ * D_], g_aol[M_ * D_];         // attn out [b,l,d] hi/lo

// ---------------------------------------------------------------------------
// Helpers
// ---------------------------------------------------------------------------
__device__ __forceinline__ void split2(float x0, float x1,
                                       unsigned& hi, unsigned& lo) {
    unsigned h;
    asm("cvt.rn.f16x2.f32 %0, %1, %2;" : "=r"(h) : "f"(x1), "f"(x0));
    __half2 hh = *reinterpret_cast<__half2*>(&h);
    float h0 = __low2float(hh), h1 = __high2float(hh);
    float r0 = x0 - h0, r1 = x1 - h1;
    unsigned l;
    asm("cvt.rn.f16x2.f32 %0, %1, %2;" : "=r"(l) : "f"(r1), "f"(r0));
    hi = h; lo = l;
}

__device__ __forceinline__ void split1(float x, f16& hi, f16& lo) {
    f16 h = __float2half_rn(x);
    hi = h;
    lo = __float2half_rn(x - __half2float(h));
}

#define MMA_F16(d, a, b)                                                      \
    asm volatile(                                                             \
        "mma.sync.aligned.m16n8k16.row.col.f32.f16.f16.f32 "                  \
        "{%0,%1,%2,%3}, {%4,%5,%6,%7}, {%8,%9}, {%0,%1,%2,%3};"               \
        : "+f"((d)[0]), "+f"((d)[1]), "+f"((d)[2]), "+f"((d)[3])              \
        : "r"((a)[0]), "r"((a)[1]), "r"((a)[2]), "r"((a)[3]),                 \
          "r"((b)[0]), "r"((b)[1]))

#define CP_ASYNC16(smem_u32, gptr)                                            \
    asm volatile("cp.async.cg.shared.global [%0], [%1], 16;"                  \
                 :: "r"(smem_u32), "l"(gptr))
#define CP_COMMIT()  asm volatile("cp.async.commit_group;" ::: "memory")
#define CP_WAIT0()   asm volatile("cp.async.wait_group 0;" ::: "memory")

__device__ __forceinline__ void ldsm4(unsigned& r0, unsigned& r1,
                                      unsigned& r2, unsigned& r3, unsigned a) {
    asm volatile("ldmatrix.sync.aligned.m8n8.x4.shared.b16 {%0,%1,%2,%3}, [%4];"
                 : "=r"(r0), "=r"(r1), "=r"(r2), "=r"(r3) : "r"(a));
}
__device__ __forceinline__ void ldsm4t(unsigned& r0, unsigned& r1,
                                       unsigned& r2, unsigned& r3, unsigned a) {
    asm volatile("ldmatrix.sync.aligned.m8n8.x4.trans.shared.b16 {%0,%1,%2,%3}, [%4];"
                 : "=r"(r0), "=r"(r1), "=r"(r2), "=r"(r3) : "r"(a));
}

// ---------------------------------------------------------------------------
// fp32 -> fp16 hi/lo split conversion (float4 per thread)
// ---------------------------------------------------------------------------
__global__ __launch_bounds__(256) void conv_split(
    const float* __restrict__ in, f16* __restrict__ hi, f16* __restrict__ lo)
{
    int i = blockIdx.x * blockDim.x + threadIdx.x;
    float4 v = ((const float4*)in)[i];
    unsigned h0, l0, h1, l1;
    split2(v.x, v.y, h0, l0);
    split2(v.z, v.w, h1, l1);
    ((uint2*)hi)[i] = make_uint2(h0, h1);
    ((uint2*)lo)[i] = make_uint2(l0, l1);
}

// ---------------------------------------------------------------------------
// 2-mma fp16 split NT GEMM (R9 — frozen, verified).
// CTA 128x128x32, 256 threads (8 warps: 2m x 4n), warp tile 64x32.
// ---------------------------------------------------------------------------
#define SB  40
#define STG (128 * SB)

__global__ __launch_bounds__(256, 2) void gemm_h2(
    const f16* __restrict__ Ah, const f16* __restrict__ Al,
    const f16* __restrict__ Wh, const f16* __restrict__ Wl,
    float* __restrict__ C, int M, int N, int K)
{
    extern __shared__ __align__(16) f16 sm[];
    const unsigned AHo = 0, ALo = 2 * STG, WHo = 4 * STG, WLo = 6 * STG;

    const int t = threadIdx.x;
    const int w = t >> 5, lane = t & 31;
    const int g = lane >> 2, qd = lane & 3;
    const int wm = (w & 1) * 64, wn = (w >> 1) * 32;
    const int bm = blockIdx.y * 128, bn = blockIdx.x * 128;

    const int laneRow = lane & 7, qR = (lane >> 3) & 1, qK = (lane >> 4) & 1;

    const int srow = t >> 1, shalf = t & 1;
    const size_t gaoff = (size_t)(bm + srow) * K + shalf * 16;
    const size_t gwoff = (size_t)(bn + srow) * K + shalf * 16;
    const unsigned smem0 = (unsigned)__cvta_generic_to_shared(sm);
    const unsigned stoff = (srow * SB + shalf * 16) * 2;
    const unsigned stageB = STG * 2;

    float acc[4][4][4];
#pragma unroll
    for (int mi = 0; mi < 4; mi++)
#pragma unroll
        for (int ni = 0; ni < 4; ni++)
#pragma unroll
            for (int k = 0; k < 4; k++) acc[mi][ni][k] = 0.0f;

#pragma unroll
    for (int j = 0; j < 2; j++) {
        CP_ASYNC16(smem0 + AHo * 2 + stoff + j * 16, Ah + gaoff + j * 8);
        CP_ASYNC16(smem0 + ALo * 2 + stoff + j * 16, Al + gaoff + j * 8);
        CP_ASYNC16(smem0 + WHo * 2 + stoff + j * 16, Wh + gwoff + j * 8);
        CP_ASYNC16(smem0 + WLo * 2 + stoff + j * 16, Wl + gwoff + j * 8);
    }
    CP_COMMIT();

    const int NK = K >> 5;
    for (int ks = 0; ks < NK; ks++) {
        CP_WAIT0();
        __syncthreads();
        if (ks + 1 < NK) {
            unsigned sB = ((ks + 1) & 1) * stageB;
            int k0 = (ks + 1) * 32;
#pragma unroll
            for (int j = 0; j < 2; j++) {
                CP_ASYNC16(smem0 + AHo * 2 + sB + stoff + j * 16, Ah + gaoff + k0 + j * 8);
                CP_ASYNC16(smem0 + ALo * 2 + sB + stoff + j * 16, Al + gaoff + k0 + j * 8);
                CP_ASYNC16(smem0 + WHo * 2 + sB + stoff + j * 16, Wh + gwoff + k0 + j * 8);
                CP_ASYNC16(smem0 + WLo * 2 + sB + stoff + j * 16, Wl + gwoff + k0 + j * 8);
            }
            CP_COMMIT();
        }
        const unsigned sB = (ks & 1) * stageB;

#pragma unroll
        for (int kc = 0; kc < 2; kc++) {
            unsigned ahf[4][4], axf[4][4];
#pragma unroll
            for (int mi = 0; mi < 4; mi++) {
                unsigned ra = ((wm + mi * 16 + laneRow + qR * 8) * SB + kc * 16 + qK * 8) * 2;
                unsigned al0, al1, al2, al3;
                ldsm4(ahf[mi][0], ahf[mi][1], ahf[mi][2], ahf[mi][3],
                      smem0 + AHo * 2 + sB + ra);
                ldsm4(al0, al1, al2, al3, smem0 + ALo * 2 + sB + ra);
                axf[mi][0] = al0; axf[mi][1] = al1;
                axf[mi][2] = ahf[mi][2]; axf[mi][3] = ahf[mi][3];
                (void)al2; (void)al3;
            }
#pragma unroll
            for (int p = 0; p < 2; p++) {
                unsigned rb = ((wn + p * 16 + laneRow + qK * 8) * SB + kc * 16 + qR * 8) * 2;
                unsigned bh[4], bl[4];
                ldsm4(bh[0], bh[1], bh[2], bh[3], smem0 + WHo * 2 + sB + rb);
                ldsm4(bl[0], bl[1], bl[2], bl[3], smem0 + WLo * 2 + sB + rb);
                unsigned bh0[2] = {bh[0], bh[1]}, bh1[2] = {bh[2], bh[3]};
                unsigned bx0[2] = {bh[0], bl[1]}, bx1[2] = {bh[2], bl[3]};
#pragma unroll
                for (int mi = 0; mi < 4; mi++) {
                    MMA_F16(acc[mi][2 * p],     ahf[mi], bh0);
                    MMA_F16(acc[mi][2 * p],     axf[mi], bx0);
                    MMA_F16(acc[mi][2 * p + 1], ahf[mi], bh1);
                    MMA_F16(acc[mi][2 * p + 1], axf[mi], bx1);
                }
            }
        }
    }

    // epilogue (fp32)
#pragma unroll
    for (int mi = 0; mi < 4; mi++)
#pragma unroll
        for (int rr = 0; rr < 2; rr++) {
            int row = bm + wm + mi * 16 + g + rr * 8;
            float* Cp = C + (size_t)row * N + bn + wn + 2 * qd;
#pragma unroll
            for (int ni = 0; ni < 4; ni++) {
                *(float2*)(Cp + ni * 8) =
                    make_float2(acc[mi][ni][2 * rr], acc[mi][ni][2 * rr + 1]);
            }
        }
}

// ---------------------------------------------------------------------------
// RoPE + split to [b,h,l,hd]; Q pre-scaled; writes fp16 hi/lo directly.
// ---------------------------------------------------------------------------
__global__ __launch_bounds__(256) void rope_split(const float* __restrict__ qkv)
{
    int idx = blockIdx.x * blockDim.x + threadIdx.x;
    int i = idx & 31;
    int l = (idx >> 5) & (L_ - 1);
    int h = (idx >> 16) & (H_ - 1);
    int b = idx >> 20;

    const float* row = qkv + (size_t)(b * L_ + l) * QKV_N;

    float inv = powf(10000.0f, -(float)(2 * i) * (1.0f / (float)HD_));
    float ang = (float)l * inv;
    float cs = cosf(ang);
    float sn = sinf(ang);

    int off = h * HD_ + 2 * i;
    float2 qv = *(const float2*)(row + off);
    float2 kv = *(const float2*)(row + D_ + off);
    float q1 = qv.x, q2 = qv.y;
    float k1 = kv.x, k2 = kv.y;

    size_t o = ((size_t)((b * H_ + h) * L_ + l)) * HD_;
    const float qscale = 0.125f;
    float qa = (q1 * cs - q2 * sn) * qscale;
    float qb = (q1 * sn + q2 * cs) * qscale;
    float ka = k1 * cs - k2 * sn;
    float kb = k1 * sn + k2 * cs;
    float va = row[2 * D_ + h * HD_ + i];
    float vb = row[2 * D_ + h * HD_ + i + 32];

    f16 hh, ll;
    split1(qa, hh, ll); g_qh[o + i] = hh;      g_ql[o + i] = ll;
    split1(qb, hh, ll); g_qh[o + i + 32] = hh; g_ql[o + i + 32] = ll;
    split1(ka, hh, ll); g_kh[o + i] = hh;      g_kl[o + i] = ll;
    split1(kb, hh, ll); g_kh[o + i + 32] = hh; g_kl[o + i + 32] = ll;
    split1(va, hh, ll); g_vh[o + i] = hh;      g_vl[o + i] = ll;
    split1(vb, hh, ll); g_vh[o + i + 32] = hh; g_vl[o + i + 32] = ll;
}

// ---------------------------------------------------------------------------
// Flash attention, fp16 2-mma split. CTA = 256 queries, 16 warps x 16 q-rows,
// 512 threads, 1 CTA/SM. K/V traffic per query halved vs 128-q tiles.
// K/V 64-chunks double-buffered. Row stride 72 els (LDSM-conflict-free).
// ---------------------------------------------------------------------------
#define SA 72
#define QROWS 256
#define QTILE (QROWS * SA)
#define KTILE (64 * SA)

__global__ __launch_bounds__(512, 1) void attn_h2()
{
    extern __shared__ __align__(16) f16 sma[];
    const unsigned QHo2 = 0, QLo2 = QTILE;
    const unsigned KHo2 = 2 * QTILE;
    const unsigned KLo2 = 2 * QTILE + 2 * KTILE;
    const unsigned VHo2 = 2 * QTILE + 4 * KTILE;
    const unsigned VLo2 = 2 * QTILE + 6 * KTILE;

    const int qblk = blockIdx.x, h = blockIdx.y, b = blockIdx.z;
    const int t = threadIdx.x, w = t >> 5, lane = t & 31;
    const int g = lane >> 2, qd = lane & 3;
    const int laneRow = lane & 7, qR = (lane >> 3) & 1, qK = (lane >> 4) & 1;

    const size_t base = ((size_t)(b * H_ + h)) * L_ * HD_;
    const f16* Qh = g_qh + base + (size_t)qblk * QROWS * HD_;
    const f16* Ql = g_ql + base + (size_t)qblk * QROWS * HD_;
    const f16* Kh = g_kh + base;
    const f16* Kl = g_kl + base;
    const f16* Vh = g_vh + base;
    const f16* Vl = g_vl + base;

    const unsigned smem0 = (unsigned)__cvta_generic_to_shared(sma);

    // Q staging: 512 threads, 256 rows, half-row (32 els = 4x16B) each
    const int qrow = t >> 1, qhalf = t & 1;
    const unsigned qoffB = (qrow * SA) * 2 + qhalf * 64;
    const size_t qgoff = (size_t)qrow * HD_ + qhalf * 32;
    // K/V staging: 64 rows, 8 threads/row, one 16B chunk per array each
    const int krow = t >> 3, kq = t & 7;
    const unsigned koffB = (krow * SA) * 2 + kq * 16;
    const size_t kgoff = (size_t)krow * HD_ + kq * 8;

#pragma unroll
    for (int j = 0; j < 4; j++) {
        CP_ASYNC16(smem0 + QHo2 * 2 + qoffB + j * 16, Qh + qgoff + j * 8);
        CP_ASYNC16(smem0 + QLo2 * 2 + qoffB + j * 16, Ql + qgoff + j * 8);
    }
    CP_ASYNC16(smem0 + KHo2 * 2 + koffB, Kh + kgoff);
    CP_ASYNC16(smem0 + KLo2 * 2 + koffB, Kl + kgoff);
    CP_ASYNC16(smem0 + VHo2 * 2 + koffB, Vh + kgoff);
    CP_ASYNC16(smem0 + VLo2 * 2 + koffB, Vl + kgoff);
    CP_COMMIT();

    float mrow[2] = {-3.0e38f, -3.0e38f};
    float lsum[2] = {0.0f, 0.0f};
    float oacc[8][4];
#pragma unroll
    for (int ni = 0; ni < 8; ni++)
#pragma unroll
        for (int k = 0; k < 4; k++) oacc[ni][k] = 0.0f;

    const int NKB = L_ / 64;
    for (int kb = 0; kb < NKB; kb++) {
        CP_WAIT0();
        __syncthreads();
        if (kb + 1 < NKB) {
            unsigned sB = ((kb + 1) & 1) * KTILE * 2;
            size_t go = (size_t)((kb + 1) * 64) * HD_ + kgoff;
            CP_ASYNC16(smem0 + KHo2 * 2 + sB + koffB, Kh + go);
            CP_ASYNC16(smem0 + KLo2 * 2 + sB + koffB, Kl + go);
            CP_ASYNC16(smem0 + VHo2 * 2 + sB + koffB, Vh + go);
            CP_ASYNC16(smem0 + VLo2 * 2 + sB + koffB, Vl + go);
            CP_COMMIT();
        }
        const unsigned sB = (kb & 1) * KTILE * 2;

        // ---- S = Q*K^T (2-mma split) ----
        float sacc[8][4];
#pragma unroll
        for (int ni = 0; ni < 8; ni++)
#pragma unroll
            for (int k = 0; k < 4; k++) sacc[ni][k] = 0.0f;

#pragma unroll
        for (int kc = 0; kc < 4; kc++) {
            unsigned qhf[4], qxf[4];
            unsigned rq = ((w * 16 + laneRow + qR * 8) * SA + kc * 16 + qK * 8) * 2;
            {
                unsigned l0, l1, l2, l3;
                ldsm4(qhf[0], qhf[1], qhf[2], qhf[3], smem0 + QHo2 * 2 + rq);
                ldsm4(l0, l1, l2, l3, smem0 + QLo2 * 2 + rq);
                qxf[0] = l0; qxf[1] = l1; qxf[2] = qhf[2]; qxf[3] = qhf[3];
                (void)l2; (void)l3;
            }
#pragma unroll
            for (int p = 0; p < 4; p++) {
                unsigned rk = ((p * 16 + laneRow + qK * 8) * SA + kc * 16 + qR * 8) * 2;
                unsigned kh[4], kl[4];
                ldsm4(kh[0], kh[1], kh[2], kh[3], smem0 + KHo2 * 2 + sB + rk);
                ldsm4(kl[0], kl[1], kl[2], kl[3], smem0 + KLo2 * 2 + sB + rk);
                unsigned kh0[2] = {kh[0], kh[1]}, kh1[2] = {kh[2], kh[3]};
                unsigned kx0[2] = {kh[0], kl[1]}, kx1[2] = {kh[2], kl[3]};
                MMA_F16(sacc[2 * p],     qhf, kh0);
                MMA_F16(sacc[2 * p],     qxf, kx0);
                MMA_F16(sacc[2 * p + 1], qhf, kh1);
                MMA_F16(sacc[2 * p + 1], qxf, kx1);
            }
        }

        // ---- online softmax ----
#pragma unroll
        for (int rr = 0; rr < 2; rr++) {
            float tm = -3.0e38f;
#pragma unroll
            for (int ni = 0; ni < 8; ni++)
                tm = fmaxf(tm, fmaxf(sacc[ni][2 * rr], sacc[ni][2 * rr + 1]));
            tm = fmaxf(tm, __shfl_xor_sync(0xffffffffu, tm, 1));
            tm = fmaxf(tm, __shfl_xor_sync(0xffffffffu, tm, 2));
            float nm = fmaxf(mrow[rr], tm);
            float sum = 0.0f;
#pragma unroll
            for (int ni = 0; ni < 8; ni++) {
                float p0 = __expf(sacc[ni][2 * rr] - nm);
                float p1 = __expf(sacc[ni][2 * rr + 1] - nm);
                sacc[ni][2 * rr] = p0;
                sacc[ni][2 * rr + 1] = p1;
                sum += p0 + p1;
            }
            sum += __shfl_xor_sync(0xffffffffu, sum, 1);
            sum += __shfl_xor_sync(0xffffffffu, sum, 2);
            float f = __expf(mrow[rr] - nm);
            lsum[rr] = lsum[rr] * f + sum;
            mrow[rr] = nm;
#pragma unroll
            for (int ni = 0; ni < 8; ni++) {
                oacc[ni][2 * rr] *= f;
                oacc[ni][2 * rr + 1] *= f;
            }
        }

        // ---- O += P*V (P from registers, 2-mma split) ----
#pragma unroll
        for (int kc = 0; kc < 4; kc++) {
            unsigned ph[4], pl[4], px[4];
            split2(sacc[2 * kc][0],     sacc[2 * kc][1],     ph[0], pl[0]);
            split2(sacc[2 * kc][2],     sacc[2 * kc][3],     ph[1], pl[1]);
            split2(sacc[2 * kc + 1][0], sacc[2 * kc + 1][1], ph[2], pl[2]);
            split2(sacc[2 * kc + 1][2], sacc[2 * kc + 1][3], ph[3], pl[3]);
            px[0] = pl[0]; px[1] = pl[1]; px[2] = ph[2]; px[3] = ph[3];
#pragma unroll
            for (int p = 0; p < 4; p++) {
                unsigned rv = ((kc * 16 + laneRow + qR * 8) * SA + p * 16 + qK * 8) * 2;
                unsigned vh[4], vl[4];
                ldsm4t(vh[0], vh[1], vh[2], vh[3], smem0 + VHo2 * 2 + sB + rv);
                ldsm4t(vl[0], vl[1], vl[2], vl[3], smem0 + VLo2 * 2 + sB + rv);
                unsigned vh0[2] = {vh[0], vh[1]}, vh1[2] = {vh[2], vh[3]};
                unsigned vx0[2] = {vh[0], vl[1]}, vx1[2] = {vh[2], vl[3]};
                MMA_F16(oacc[2 * p],     ph, vh0);
                MMA_F16(oacc[2 * p],     px, vx0);
                MMA_F16(oacc[2 * p + 1], ph, vh1);
                MMA_F16(oacc[2 * p + 1], px, vx1);
            }
        }
    }

    // epilogue: normalize, split to fp16 hi/lo, write [b,l,d]
#pragma unroll
    for (int rr = 0; rr < 2; rr++) {
        int row = qblk * QROWS + w * 16 + g + rr * 8;
        float inv = 1.0f / lsum[rr];
        unsigned* oh = (unsigned*)(g_aoh + (size_t)(b * L_ + row) * D_ + h * HD_);
        unsigned* ol = (unsigned*)(g_aol + (size_t)(b * L_ + row) * D_ + h * HD_);
#pragma unroll
        for (int ni = 0; ni < 8; ni++) {
            unsigned hv, lv;
            split2(oacc[ni][2 * rr] * inv, oacc[ni][2 * rr + 1] * inv, hv, lv);
            oh[ni * 4 + qd] = hv;
            ol[ni * 4 + qd] = lv;
        }
    }
}

// ---------------------------------------------------------------------------
// Launcher
// ---------------------------------------------------------------------------
extern "C" void kernel_launch(void* const* d_in, const int* in_sizes, int n_in,
                              void* d_out, int out_size)
{
    const float* x     = (const float*)d_in[0];
    const float* Wqkv  = (const float*)d_in[1];
    const float* Wproj = (const float*)d_in[2];
    float* out = (float*)d_out;

    float* qkv_p;
    f16 *xh, *xl, *wqh, *wql, *wph, *wpl, *aoh, *aol;
    cudaGetSymbolAddress((void**)&qkv_p, g_qkv);
    cudaGetSymbolAddress((void**)&xh,  g_xh);  cudaGetSymbolAddress((void**)&xl,  g_xl);
    cudaGetSymbolAddress((void**)&wqh, g_wqh); cudaGetSymbolAddress((void**)&wql, g_wql);
    cudaGetSymbolAddress((void**)&wph, g_wph); cudaGetSymbolAddress((void**)&wpl, g_wpl);
    cudaGetSymbolAddress((void**)&aoh, g_aoh); cudaGetSymbolAddress((void**)&aol, g_aol);

    const int smem_gemm = 8 * STG * sizeof(f16);                     // 81920
    const int smem_attn = (2 * QTILE + 8 * KTILE) * sizeof(f16);     // 147456
    cudaFuncSetAttribute(gemm_h2, cudaFuncAttributeMaxDynamicSharedMemorySize, smem_gemm);
    cudaFuncSetAttribute(attn_h2, cudaFuncAttributeMaxDynamicSharedMemorySize, smem_attn);

    // 0) pre-split inputs to fp16 hi/lo
    conv_split<<<(M_ * D_ / 4) / 256, 256>>>(x, xh, xl);
    conv_split<<<(QKV_N * D_ / 4) / 256, 256>>>(Wqkv, wqh, wql);
    conv_split<<<(D_ * D_ / 4) / 256, 256>>>(Wproj, wph, wpl);

    // 1) QKV projection (fp32 out)
    gemm_h2<<<dim3(QKV_N / 128, M_ / 128), 256, smem_gemm>>>(
        xh, xl, wqh, wql, qkv_p, M_, QKV_N, D_);

    // 2) RoPE + split to fp16 hi/lo [b,h,l,hd]
    rope_split<<<(B_ * H_ * L_ * 32) / 256, 256>>>(qkv_p);

    // 3) Attention (256-q tiles)
    attn_h2<<<dim3(L_ / QROWS, H_, B_), 512, smem_attn>>>();

    // 4) Output projection (fp32 out)
    gemm_h2<<<dim3(D_ / 128, M_ / 128), 256, smem_gemm>>>(
        aoh, aol, wph, wpl, out, M_, D_, D_);
}

// round 16
// speedup vs baseline: 1.0381x; 1.0381x over previous
#include <cuda_runtime.h>
#include <cuda_fp16.h>
#include <math.h>

// Problem constants
#define B_  4
#define L_  2048
#define D_  1024
#define H_  16
#define HD_ 64
#define M_  (B_ * L_)          // 8192
#define QKV_N (3 * D_)         // 3072

typedef __half f16;

// ---------------------------------------------------------------------------
// Scratch (device globals)
// ---------------------------------------------------------------------------
__device__ float g_qkv[M_ * QKV_N];                    // fp32 qkv rows
__device__ f16 g_xh[M_ * D_],     g_xl[M_ * D_];       // x hi/lo
__device__ f16 g_wqh[QKV_N * D_], g_wql[QKV_N * D_];   // W_qkv hi/lo
__device__ f16 g_wph[D_ * D_],    g_wpl[D_ * D_];      // W_proj hi/lo
__device__ f16 g_qh[M_ * D_], g_ql[M_ * D_];           // Q [b,h,l,hd] hi/lo
__device__ f16 g_kh[M_ * D_], g_kl[M_ * D_];           // K
__device__ f16 g_vh[M_ * D_], g_vl[M_ * D_];           // V
__device__ f16 g_aoh[M_ * D_], g_aol[M_ * D_];         // attn out [b,l,d] hi/lo
__device__ float g_cs[L_ * 32], g_sn[L_ * 32];         // rope tables [l][i]

// ---------------------------------------------------------------------------
// Helpers
// ---------------------------------------------------------------------------
__device__ __forceinline__ void split2(float x0, float x1,
                                       unsigned& hi, unsigned& lo) {
    unsigned h;
    asm("cvt.rn.f16x2.f32 %0, %1, %2;" : "=r"(h) : "f"(x1), "f"(x0));
    __half2 hh = *reinterpret_cast<__half2*>(&h);
    float h0 = __low2float(hh), h1 = __high2float(hh);
    float r0 = x0 - h0, r1 = x1 - h1;
    unsigned l;
    asm("cvt.rn.f16x2.f32 %0, %1, %2;" : "=r"(l) : "f"(r1), "f"(r0));
    hi = h; lo = l;
}

__device__ __forceinline__ void split1(float x, f16& hi, f16& lo) {
    f16 h = __float2half_rn(x);
    hi = h;
    lo = __float2half_rn(x - __half2float(h));
}

#define MMA_F16(d, a, b)                                                      \
    asm volatile(                                                             \
        "mma.sync.aligned.m16n8k16.row.col.f32.f16.f16.f32 "                  \
        "{%0,%1,%2,%3}, {%4,%5,%6,%7}, {%8,%9}, {%0,%1,%2,%3};"               \
        : "+f"((d)[0]), "+f"((d)[1]), "+f"((d)[2]), "+f"((d)[3])              \
        : "r"((a)[0]), "r"((a)[1]), "r"((a)[2]), "r"((a)[3]),                 \
          "r"((b)[0]), "r"((b)[1]))

#define CP_ASYNC16(smem_u32, gptr)                                            \
    asm volatile("cp.async.cg.shared.global [%0], [%1], 16;"                  \
                 :: "r"(smem_u32), "l"(gptr))
#define CP_COMMIT()  asm volatile("cp.async.commit_group;" ::: "memory")
#define CP_WAIT0()   asm volatile("cp.async.wait_group 0;" ::: "memory")

__device__ __forceinline__ void ldsm4(unsigned& r0, unsigned& r1,
                                      unsigned& r2, unsigned& r3, unsigned a) {
    asm volatile("ldmatrix.sync.aligned.m8n8.x4.shared.b16 {%0,%1,%2,%3}, [%4];"
                 : "=r"(r0), "=r"(r1), "=r"(r2), "=r"(r3) : "r"(a));
}
__device__ __forceinline__ void ldsm4t(unsigned& r0, unsigned& r1,
                                       unsigned& r2, unsigned& r3, unsigned a) {
    asm volatile("ldmatrix.sync.aligned.m8n8.x4.trans.shared.b16 {%0,%1,%2,%3}, [%4];"
                 : "=r"(r0), "=r"(r1), "=r"(r2), "=r"(r3) : "r"(a));
}

// ---------------------------------------------------------------------------
// fp32 -> fp16 hi/lo split conversion (float4 per thread)
// ---------------------------------------------------------------------------
__global__ __launch_bounds__(256) void conv_split(
    const float* __restrict__ in, f16* __restrict__ hi, f16* __restrict__ lo)
{
    int i = blockIdx.x * blockDim.x + threadIdx.x;
    float4 v = ((const float4*)in)[i];
    unsigned h0, l0, h1, l1;
    split2(v.x, v.y, h0, l0);
    split2(v.z, v.w, h1, l1);
    ((uint2*)hi)[i] = make_uint2(h0, h1);
    ((uint2*)lo)[i] = make_uint2(l0, l1);
}

// ---------------------------------------------------------------------------
// RoPE cos/sin tables (identical math to the previous inline computation)
// ---------------------------------------------------------------------------
__global__ __launch_bounds__(256) void rope_table()
{
    int idx = blockIdx.x * blockDim.x + threadIdx.x;   // 65536
    int l = idx >> 5, i = idx & 31;
    float inv = powf(10000.0f, -(float)(2 * i) * (1.0f / (float)HD_));
    float ang = (float)l * inv;
    g_cs[idx] = cosf(ang);
    g_sn[idx] = sinf(ang);
}

// ---------------------------------------------------------------------------
// 2-mma fp16 split NT GEMM (R9 — frozen, verified).
// CTA 128x128x32, 256 threads (8 warps: 2m x 4n), warp tile 64x32.
// ---------------------------------------------------------------------------
#define SB  40
#define STG (128 * SB)

__global__ __launch_bounds__(256, 2) void gemm_h2(
    const f16* __restrict__ Ah, const f16* __restrict__ Al,
    const f16* __restrict__ Wh, const f16* __restrict__ Wl,
    float* __restrict__ C, int M, int N, int K)
{
    extern __shared__ __align__(16) f16 sm[];
    const unsigned AHo = 0, ALo = 2 * STG, WHo = 4 * STG, WLo = 6 * STG;

    const int t = threadIdx.x;
    const int w = t >> 5, lane = t & 31;
    const int g = lane >> 2, qd = lane & 3;
    const int wm = (w & 1) * 64, wn = (w >> 1) * 32;
    const int bm = blockIdx.y * 128, bn = blockIdx.x * 128;

    const int laneRow = lane & 7, qR = (lane >> 3) & 1, qK = (lane >> 4) & 1;

    const int srow = t >> 1, shalf = t & 1;
    const size_t gaoff = (size_t)(bm + srow) * K + shalf * 16;
    const size_t gwoff = (size_t)(bn + srow) * K + shalf * 16;
    const unsigned smem0 = (unsigned)__cvta_generic_to_shared(sm);
    const unsigned stoff = (srow * SB + shalf * 16) * 2;
    const unsigned stageB = STG * 2;

    float acc[4][4][4];
#pragma unroll
    for (int mi = 0; mi < 4; mi++)
#pragma unroll
        for (int ni = 0; ni < 4; ni++)
#pragma unroll
            for (int k = 0; k < 4; k++) acc[mi][ni][k] = 0.0f;

#pragma unroll
    for (int j = 0; j < 2; j++) {
        CP_ASYNC16(smem0 + AHo * 2 + stoff + j * 16, Ah + gaoff + j * 8);
        CP_ASYNC16(smem0 + ALo * 2 + stoff + j * 16, Al + gaoff + j * 8);
        CP_ASYNC16(smem0 + WHo * 2 + stoff + j * 16, Wh + gwoff + j * 8);
        CP_ASYNC16(smem0 + WLo * 2 + stoff + j * 16, Wl + gwoff + j * 8);
    }
    CP_COMMIT();

    const int NK = K >> 5;
    for (int ks = 0; ks < NK; ks++) {
        CP_WAIT0();
        __syncthreads();
        if (ks + 1 < NK) {
            unsigned sB = ((ks + 1) & 1) * stageB;
            int k0 = (ks + 1) * 32;
#pragma unroll
            for (int j = 0; j < 2; j++) {
                CP_ASYNC16(smem0 + AHo * 2 + sB + stoff + j * 16, Ah + gaoff + k0 + j * 8);
                CP_ASYNC16(smem0 + ALo * 2 + sB + stoff + j * 16, Al + gaoff + k0 + j * 8);
                CP_ASYNC16(smem0 + WHo * 2 + sB + stoff + j * 16, Wh + gwoff + k0 + j * 8);
                CP_ASYNC16(smem0 + WLo * 2 + sB + stoff + j * 16, Wl + gwoff + k0 + j * 8);
            }
            CP_COMMIT();
        }
        const unsigned sB = (ks & 1) * stageB;

#pragma unroll
        for (int kc = 0; kc < 2; kc++) {
            unsigned ahf[4][4], axf[4][4];
#pragma unroll
            for (int mi = 0; mi < 4; mi++) {
                unsigned ra = ((wm + mi * 16 + laneRow + qR * 8) * SB + kc * 16 + qK * 8) * 2;
                unsigned al0, al1, al2, al3;
                ldsm4(ahf[mi][0], ahf[mi][1], ahf[mi][2], ahf[mi][3],
                      smem0 + AHo * 2 + sB + ra);
                ldsm4(al0, al1, al2, al3, smem0 + ALo * 2 + sB + ra);
                axf[mi][0] = al0; axf[mi][1] = al1;
                axf[mi][2] = ahf[mi][2]; axf[mi][3] = ahf[mi][3];
                (void)al2; (void)al3;
            }
#pragma unroll
            for (int p = 0; p < 2; p++) {
                unsigned rb = ((wn + p * 16 + laneRow + qK * 8) * SB + kc * 16 + qR * 8) * 2;
                unsigned bh[4], bl[4];
                ldsm4(bh[0], bh[1], bh[2], bh[3], smem0 + WHo * 2 + sB + rb);
                ldsm4(bl[0], bl[1], bl[2], bl[3], smem0 + WLo * 2 + sB + rb);
                unsigned bh0[2] = {bh[0], bh[1]}, bh1[2] = {bh[2], bh[3]};
                unsigned bx0[2] = {bh[0], bl[1]}, bx1[2] = {bh[2], bl[3]};
#pragma unroll
                for (int mi = 0; mi < 4; mi++) {
                    MMA_F16(acc[mi][2 * p],     ahf[mi], bh0);
                    MMA_F16(acc[mi][2 * p],     axf[mi], bx0);
                    MMA_F16(acc[mi][2 * p + 1], ahf[mi], bh1);
                    MMA_F16(acc[mi][2 * p + 1], axf[mi], bx1);
                }
            }
        }
    }

    // epilogue (fp32)
#pragma unroll
    for (int mi = 0; mi < 4; mi++)
#pragma unroll
        for (int rr = 0; rr < 2; rr++) {
            int row = bm + wm + mi * 16 + g + rr * 8;
            float* Cp = C + (size_t)row * N + bn + wn + 2 * qd;
#pragma unroll
            for (int ni = 0; ni < 4; ni++) {
                *(float2*)(Cp + ni * 8) =
                    make_float2(acc[mi][ni][2 * rr], acc[mi][ni][2 * rr + 1]);
            }
        }
}

// ---------------------------------------------------------------------------
// RoPE + split to [b,h,l,hd]; Q pre-scaled; cos/sin from table (identical
// values); writes fp16 hi/lo directly.
// ---------------------------------------------------------------------------
__global__ __launch_bounds__(256) void rope_split(const float* __restrict__ qkv)
{
    int idx = blockIdx.x * blockDim.x + threadIdx.x;
    int i = idx & 31;
    int l = (idx >> 5) & (L_ - 1);
    int h = (idx >> 16) & (H_ - 1);
    int b = idx >> 20;

    const float* row = qkv + (size_t)(b * L_ + l) * QKV_N;

    float cs = g_cs[l * 32 + i];
    float sn = g_sn[l * 32 + i];

    int off = h * HD_ + 2 * i;
    float2 qv = *(const float2*)(row + off);
    float2 kv = *(const float2*)(row + D_ + off);
    float q1 = qv.x, q2 = qv.y;
    float k1 = kv.x, k2 = kv.y;

    size_t o = ((size_t)((b * H_ + h) * L_ + l)) * HD_;
    const float qscale = 0.125f;
    float qa = (q1 * cs - q2 * sn) * qscale;
    float qb = (q1 * sn + q2 * cs) * qscale;
    float ka = k1 * cs - k2 * sn;
    float kb = k1 * sn + k2 * cs;
    float va = row[2 * D_ + h * HD_ + i];
    float vb = row[2 * D_ + h * HD_ + i + 32];

    f16 hh, ll;
    split1(qa, hh, ll); g_qh[o + i] = hh;      g_ql[o + i] = ll;
    split1(qb, hh, ll); g_qh[o + i + 32] = hh; g_ql[o + i + 32] = ll;
    split1(ka, hh, ll); g_kh[o + i] = hh;      g_kl[o + i] = ll;
    split1(kb, hh, ll); g_kh[o + i + 32] = hh; g_kl[o + i + 32] = ll;
    split1(va, hh, ll); g_vh[o + i] = hh;      g_vl[o + i] = ll;
    split1(vb, hh, ll); g_vh[o + i + 32] = hh; g_vl[o + i + 32] = ll;
}

// ---------------------------------------------------------------------------
// Flash attention, fp16 2-mma split (R14 — frozen, verified).
// CTA = 128 queries, 8 warps x 16 q-rows, 256 threads, 2 CTAs/SM.
// ---------------------------------------------------------------------------
#define SA 72
#define QTILE (128 * SA)
#define KTILE (64 * SA)

__global__ __launch_bounds__(256, 2) void attn_h2()
{
    extern __shared__ __align__(16) f16 sma[];
    const unsigned QHo2 = 0, QLo2 = QTILE;
    const unsigned KHo2 = 2 * QTILE;
    const unsigned KLo2 = 2 * QTILE + 2 * KTILE;
    const unsigned VHo2 = 2 * QTILE + 4 * KTILE;
    const unsigned VLo2 = 2 * QTILE + 6 * KTILE;

    const int qblk = blockIdx.x, h = blockIdx.y, b = blockIdx.z;
    const int t = threadIdx.x, w = t >> 5, lane = t & 31;
    const int g = lane >> 2, qd = lane & 3;
    const int laneRow = lane & 7, qR = (lane >> 3) & 1, qK = (lane >> 4) & 1;

    const size_t base = ((size_t)(b * H_ + h)) * L_ * HD_;
    const f16* Qh = g_qh + base + (size_t)qblk * 128 * HD_;
    const f16* Ql = g_ql + base + (size_t)qblk * 128 * HD_;
    const f16* Kh = g_kh + base;
    const f16* Kl = g_kl + base;
    const f16* Vh = g_vh + base;
    const f16* Vl = g_vl + base;

    const unsigned smem0 = (unsigned)__cvta_generic_to_shared(sma);

    const int qrow = t >> 1, qhalf = t & 1;
    const unsigned qoffB = (qrow * SA) * 2 + qhalf * 64;
    const size_t qgoff = (size_t)qrow * HD_ + qhalf * 32;
    const int krow = t >> 2, kq = t & 3;
    const unsigned koffB = (krow * SA) * 2 + kq * 32;
    const size_t kgoff = (size_t)krow * HD_ + kq * 16;

#pragma unroll
    for (int j = 0; j < 4; j++) {
        CP_ASYNC16(smem0 + QHo2 * 2 + qoffB + j * 16, Qh + qgoff + j * 8);
        CP_ASYNC16(smem0 + QLo2 * 2 + qoffB + j * 16, Ql + qgoff + j * 8);
    }
#pragma unroll
    for (int j = 0; j < 2; j++) {
        CP_ASYNC16(smem0 + KHo2 * 2 + koffB + j * 16, Kh + kgoff + j * 8);
        CP_ASYNC16(smem0 + KLo2 * 2 + koffB + j * 16, Kl + kgoff + j * 8);
        CP_ASYNC16(smem0 + VHo2 * 2 + koffB + j * 16, Vh + kgoff + j * 8);
        CP_ASYNC16(smem0 + VLo2 * 2 + koffB + j * 16, Vl + kgoff + j * 8);
    }
    CP_COMMIT();

    float mrow[2] = {-3.0e38f, -3.0e38f};
    float lsum[2] = {0.0f, 0.0f};
    float oacc[8][4];
#pragma unroll
    for (int ni = 0; ni < 8; ni++)
#pragma unroll
        for (int k = 0; k < 4; k++) oacc[ni][k] = 0.0f;

    const int NKB = L_ / 64;
    for (int kb = 0; kb < NKB; kb++) {
        CP_WAIT0();
        __syncthreads();
        if (kb + 1 < NKB) {
            unsigned sB = ((kb + 1) & 1) * KTILE * 2;
            size_t go = (size_t)((kb + 1) * 64) * HD_ + kgoff;
#pragma unroll
            for (int j = 0; j < 2; j++) {
                CP_ASYNC16(smem0 + KHo2 * 2 + sB + koffB + j * 16, Kh + go + j * 8);
                CP_ASYNC16(smem0 + KLo2 * 2 + sB + koffB + j * 16, Kl + go + j * 8);
                CP_ASYNC16(smem0 + VHo2 * 2 + sB + koffB + j * 16, Vh + go + j * 8);
                CP_ASYNC16(smem0 + VLo2 * 2 + sB + koffB + j * 16, Vl + go + j * 8);
            }
            CP_COMMIT();
        }
        const unsigned sB = (kb & 1) * KTILE * 2;

        // ---- S = Q*K^T (2-mma split) ----
        float sacc[8][4];
#pragma unroll
        for (int ni = 0; ni < 8; ni++)
#pragma unroll
            for (int k = 0; k < 4; k++) sacc[ni][k] = 0.0f;

#pragma unroll
        for (int kc = 0; kc < 4; kc++) {
            unsigned qhf[4], qxf[4];
            unsigned rq = ((w * 16 + laneRow + qR * 8) * SA + kc * 16 + qK * 8) * 2;
            {
                unsigned l0, l1, l2, l3;
                ldsm4(qhf[0], qhf[1], qhf[2], qhf[3], smem0 + QHo2 * 2 + rq);
                ldsm4(l0, l1, l2, l3, smem0 + QLo2 * 2 + rq);
                qxf[0] = l0; qxf[1] = l1; qxf[2] = qhf[2]; qxf[3] = qhf[3];
                (void)l2; (void)l3;
            }
#pragma unroll
            for (int p = 0; p < 4; p++) {
                unsigned rk = ((p * 16 + laneRow + qK * 8) * SA + kc * 16 + qR * 8) * 2;
                unsigned kh[4], kl[4];
                ldsm4(kh[0], kh[1], kh[2], kh[3], smem0 + KHo2 * 2 + sB + rk);
                ldsm4(kl[0], kl[1], kl[2], kl[3], smem0 + KLo2 * 2 + sB + rk);
                unsigned kh0[2] = {kh[0], kh[1]}, kh1[2] = {kh[2], kh[3]};
                unsigned kx0[2] = {kh[0], kl[1]}, kx1[2] = {kh[2], kl[3]};
                MMA_F16(sacc[2 * p],     qhf, kh0);
                MMA_F16(sacc[2 * p],     qxf, kx0);
                MMA_F16(sacc[2 * p + 1], qhf, kh1);
                MMA_F16(sacc[2 * p + 1], qxf, kx1);
            }
        }

        // ---- online softmax ----
#pragma unroll
        for (int rr = 0; rr < 2; rr++) {
            float tm = -3.0e38f;
#pragma unroll
            for (int ni = 0; ni < 8; ni++)
                tm = fmaxf(tm, fmaxf(sacc[ni][2 * rr], sacc[ni][2 * rr + 1]));
            tm = fmaxf(tm, __shfl_xor_sync(0xffffffffu, tm, 1));
            tm = fmaxf(tm, __shfl_xor_sync(0xffffffffu, tm, 2));
            float nm = fmaxf(mrow[rr], tm);
            float sum = 0.0f;
#pragma unroll
            for (int ni = 0; ni < 8; ni++) {
                float p0 = __expf(sacc[ni][2 * rr] - nm);
                float p1 = __expf(sacc[ni][2 * rr + 1] - nm);
                sacc[ni][2 * rr] = p0;
                sacc[ni][2 * rr + 1] = p1;
                sum += p0 + p1;
            }
            sum += __shfl_xor_sync(0xffffffffu, sum, 1);
            sum += __shfl_xor_sync(0xffffffffu, sum, 2);
            float f = __expf(mrow[rr] - nm);
            lsum[rr] = lsum[rr] * f + sum;
            mrow[rr] = nm;
#pragma unroll
            for (int ni = 0; ni < 8; ni++) {
                oacc[ni][2 * rr] *= f;
                oacc[ni][2 * rr + 1] *= f;
            }
        }

        // ---- O += P*V (P from registers, 2-mma split) ----
#pragma unroll
        for (int kc = 0; kc < 4; kc++) {
            unsigned ph[4], pl[4], px[4];
            split2(sacc[2 * kc][0],     sacc[2 * kc][1],     ph[0], pl[0]);
            split2(sacc[2 * kc][2],     sacc[2 * kc][3],     ph[1], pl[1]);
            split2(sacc[2 * kc + 1][0], sacc[2 * kc + 1][1], ph[2], pl[2]);
            split2(sacc[2 * kc + 1][2], sacc[2 * kc + 1][3], ph[3], pl[3]);
            px[0] = pl[0]; px[1] = pl[1]; px[2] = ph[2]; px[3] = ph[3];
#pragma unroll
            for (int p = 0; p < 4; p++) {
                unsigned rv = ((kc * 16 + laneRow + qR * 8) * SA + p * 16 + qK * 8) * 2;
                unsigned vh[4], vl[4];
                ldsm4t(vh[0], vh[1], vh[2], vh[3], smem0 + VHo2 * 2 + sB + rv);
                ldsm4t(vl[0], vl[1], vl[2], vl[3], smem0 + VLo2 * 2 + sB + rv);
                unsigned vh0[2] = {vh[0], vh[1]}, vh1[2] = {vh[2], vh[3]};
                unsigned vx0[2] = {vh[0], vl[1]}, vx1[2] = {vh[2], vl[3]};
                MMA_F16(oacc[2 * p],     ph, vh0);
                MMA_F16(oacc[2 * p],     px, vx0);
                MMA_F16(oacc[2 * p + 1], ph, vh1);
                MMA_F16(oacc[2 * p + 1], px, vx1);
            }
        }
    }

    // epilogue: normalize, split to fp16 hi/lo, write [b,l,d]
#pragma unroll
    for (int rr = 0; rr < 2; rr++) {
        int row = qblk * 128 + w * 16 + g + rr * 8;
        float inv = 1.0f / lsum[rr];
        unsigned* oh = (unsigned*)(g_aoh + (size_t)(b * L_ + row) * D_ + h * HD_);
        unsigned* ol = (unsigned*)(g_aol + (size_t)(b * L_ + row) * D_ + h * HD_);
#pragma unroll
        for (int ni = 0; ni < 8; ni++) {
            unsigned hv, lv;
            split2(oacc[ni][2 * rr] * inv, oacc[ni][2 * rr + 1] * inv, hv, lv);
            oh[ni * 4 + qd] = hv;
            ol[ni * 4 + qd] = lv;
        }
    }
}

// ---------------------------------------------------------------------------
// Launcher
// ---------------------------------------------------------------------------
extern "C" void kernel_launch(void* const* d_in, const int* in_sizes, int n_in,
                              void* d_out, int out_size)
{
    const float* x     = (const float*)d_in[0];
    const float* Wqkv  = (const float*)d_in[1];
    const float* Wproj = (const float*)d_in[2];
    float* out = (float*)d_out;

    float* qkv_p;
    f16 *xh, *xl, *wqh, *wql, *wph, *wpl, *aoh, *aol;
    cudaGetSymbolAddress((void**)&qkv_p, g_qkv);
    cudaGetSymbolAddress((void**)&xh,  g_xh);  cudaGetSymbolAddress((void**)&xl,  g_xl);
    cudaGetSymbolAddress((void**)&wqh, g_wqh); cudaGetSymbolAddress((void**)&wql, g_wql);
    cudaGetSymbolAddress((void**)&wph, g_wph); cudaGetSymbolAddress((void**)&wpl, g_wpl);
    cudaGetSymbolAddress((void**)&aoh, g_aoh); cudaGetSymbolAddress((void**)&aol, g_aol);

    const int smem_gemm = 8 * STG * sizeof(f16);                     // 81920
    const int smem_attn = (2 * QTILE + 8 * KTILE) * sizeof(f16);     // 110592
    cudaFuncSetAttribute(gemm_h2, cudaFuncAttributeMaxDynamicSharedMemorySize, smem_gemm);
    cudaFuncSetAttribute(attn_h2, cudaFuncAttributeMaxDynamicSharedMemorySize, smem_attn);

    // 0) rope tables + pre-split inputs to fp16 hi/lo
    rope_table<<<(L_ * 32) / 256, 256>>>();
    conv_split<<<(M_ * D_ / 4) / 256, 256>>>(x, xh, xl);
    conv_split<<<(QKV_N * D_ / 4) / 256, 256>>>(Wqkv, wqh, wql);
    conv_split<<<(D_ * D_ / 4) / 256, 256>>>(Wproj, wph, wpl);

    // 1) QKV projection (fp32 out)
    gemm_h2<<<dim3(QKV_N / 128, M_ / 128), 256, smem_gemm>>>(
        xh, xl, wqh, wql, qkv_p, M_, QKV_N, D_);

    // 2) RoPE + split to fp16 hi/lo [b,h,l,hd]
    rope_split<<<(B_ * H_ * L_ * 32) / 256, 256>>>(qkv_p);

    // 3) Attention (128-q tiles, 2 CTAs/SM)
    attn_h2<<<dim3(L_ / 128, H_, B_), 256, smem_attn>>>();

    // 4) Output projection (fp32 out)
    gemm_h2<<<dim3(D_ / 128, M_ / 128), 256, smem_gemm>>>(
        aoh, aol, wph, wpl, out, M_, D_, D_);
}

// round 17
// speedup vs baseline: 1.0382x; 1.0000x over previous
#include <cuda_runtime.h>
#include <cuda_fp16.h>
#include <math.h>

// Problem constants
#define B_  4
#define L_  2048
#define D_  1024
#define H_  16
#define HD_ 64
#define M_  (B_ * L_)          // 8192
#define QKV_N (3 * D_)         // 3072

typedef __half f16;

// ---------------------------------------------------------------------------
// Scratch (device globals)
// ---------------------------------------------------------------------------
__device__ float g_qkv[M_ * QKV_N];                    // fp32 qkv rows
__device__ f16 g_xh[M_ * D_],     g_xl[M_ * D_];       // x hi/lo
__device__ f16 g_wqh[QKV_N * D_], g_wql[QKV_N * D_];   // W_qkv hi/lo
__device__ f16 g_wph[D_ * D_],    g_wpl[D_ * D_];      // W_proj hi/lo
__device__ f16 g_qh[M_ * D_], g_ql[M_ * D_];           // Q [b,h,l,hd] hi/lo
__device__ f16 g_kh[M_ * D_], g_kl[M_ * D_];           // K
__device__ f16 g_vh[M_ * D_], g_vl[M_ * D_];           // V
__device__ f16 g_aoh[M_ * D_], g_aol[M_ * D_];         // attn out [b,l,d] hi/lo
__device__ float g_cs[L_ * 32], g_sn[L_ * 32];         // rope tables [l][i]

// ---------------------------------------------------------------------------
// Helpers
// ---------------------------------------------------------------------------
__device__ __forceinline__ void split2(float x0, float x1,
                                       unsigned& hi, unsigned& lo) {
    unsigned h;
    asm("cvt.rn.f16x2.f32 %0, %1, %2;" : "=r"(h) : "f"(x1), "f"(x0));
    __half2 hh = *reinterpret_cast<__half2*>(&h);
    float h0 = __low2float(hh), h1 = __high2float(hh);
    float r0 = x0 - h0, r1 = x1 - h1;
    unsigned l;
    asm("cvt.rn.f16x2.f32 %0, %1, %2;" : "=r"(l) : "f"(r1), "f"(r0));
    hi = h; lo = l;
}

// hi-only pack: identical hi bits to split2, no residual computation.
__device__ __forceinline__ unsigned pack2(float x0, float x1) {
    unsigned h;
    asm("cvt.rn.f16x2.f32 %0, %1, %2;" : "=r"(h) : "f"(x1), "f"(x0));
    return h;
}

__device__ __forceinline__ void split1(float x, f16& hi, f16& lo) {
    f16 h = __float2half_rn(x);
    hi = h;
    lo = __float2half_rn(x - __half2float(h));
}

#define MMA_F16(d, a, b)                                                      \
    asm volatile(                                                             \
        "mma.sync.aligned.m16n8k16.row.col.f32.f16.f16.f32 "                  \
        "{%0,%1,%2,%3}, {%4,%5,%6,%7}, {%8,%9}, {%0,%1,%2,%3};"               \
        : "+f"((d)[0]), "+f"((d)[1]), "+f"((d)[2]), "+f"((d)[3])              \
        : "r"((a)[0]), "r"((a)[1]), "r"((a)[2]), "r"((a)[3]),                 \
          "r"((b)[0]), "r"((b)[1]))

#define CP_ASYNC16(smem_u32, gptr)                                            \
    asm volatile("cp.async.cg.shared.global [%0], [%1], 16;"                  \
                 :: "r"(smem_u32), "l"(gptr))
#define CP_COMMIT()  asm volatile("cp.async.commit_group;" ::: "memory")
#define CP_WAIT0()   asm volatile("cp.async.wait_group 0;" ::: "memory")

__device__ __forceinline__ void ldsm4(unsigned& r0, unsigned& r1,
                                      unsigned& r2, unsigned& r3, unsigned a) {
    asm volatile("ldmatrix.sync.aligned.m8n8.x4.shared.b16 {%0,%1,%2,%3}, [%4];"
                 : "=r"(r0), "=r"(r1), "=r"(r2), "=r"(r3) : "r"(a));
}
__device__ __forceinline__ void ldsm4t(unsigned& r0, unsigned& r1,
                                       unsigned& r2, unsigned& r3, unsigned a) {
    asm volatile("ldmatrix.sync.aligned.m8n8.x4.trans.shared.b16 {%0,%1,%2,%3}, [%4];"
                 : "=r"(r0), "=r"(r1), "=r"(r2), "=r"(r3) : "r"(a));
}

// ---------------------------------------------------------------------------
// fp32 -> fp16 hi/lo split conversion (float4 per thread)
// ---------------------------------------------------------------------------
__global__ __launch_bounds__(256) void conv_split(
    const float* __restrict__ in, f16* __restrict__ hi, f16* __restrict__ lo)
{
    int i = blockIdx.x * blockDim.x + threadIdx.x;
    float4 v = ((const float4*)in)[i];
    unsigned h0, l0, h1, l1;
    split2(v.x, v.y, h0, l0);
    split2(v.z, v.w, h1, l1);
    ((uint2*)hi)[i] = make_uint2(h0, h1);
    ((uint2*)lo)[i] = make_uint2(l0, l1);
}

// ---------------------------------------------------------------------------
// RoPE cos/sin tables (identical math to the original inline computation)
// ---------------------------------------------------------------------------
__global__ __launch_bounds__(256) void rope_table()
{
    int idx = blockIdx.x * blockDim.x + threadIdx.x;   // 65536
    int l = idx >> 5, i = idx & 31;
    float inv = powf(10000.0f, -(float)(2 * i) * (1.0f / (float)HD_));
    float ang = (float)l * inv;
    g_cs[idx] = cosf(ang);
    g_sn[idx] = sinf(ang);
}

// ---------------------------------------------------------------------------
// 2-mma fp16 split NT GEMM (R9 — frozen, verified).
// CTA 128x128x32, 256 threads (8 warps: 2m x 4n), warp tile 64x32.
// ---------------------------------------------------------------------------
#define SB  40
#define STG (128 * SB)

__global__ __launch_bounds__(256, 2) void gemm_h2(
    const f16* __restrict__ Ah, const f16* __restrict__ Al,
    const f16* __restrict__ Wh, const f16* __restrict__ Wl,
    float* __restrict__ C, int M, int N, int K)
{
    extern __shared__ __align__(16) f16 sm[];
    const unsigned AHo = 0, ALo = 2 * STG, WHo = 4 * STG, WLo = 6 * STG;

    const int t = threadIdx.x;
    const int w = t >> 5, lane = t & 31;
    const int g = lane >> 2, qd = lane & 3;
    const int wm = (w & 1) * 64, wn = (w >> 1) * 32;
    const int bm = blockIdx.y * 128, bn = blockIdx.x * 128;

    const int laneRow = lane & 7, qR = (lane >> 3) & 1, qK = (lane >> 4) & 1;

    const int srow = t >> 1, shalf = t & 1;
    const size_t gaoff = (size_t)(bm + srow) * K + shalf * 16;
    const size_t gwoff = (size_t)(bn + srow) * K + shalf * 16;
    const unsigned smem0 = (unsigned)__cvta_generic_to_shared(sm);
    const unsigned stoff = (srow * SB + shalf * 16) * 2;
    const unsigned stageB = STG * 2;

    float acc[4][4][4];
#pragma unroll
    for (int mi = 0; mi < 4; mi++)
#pragma unroll
        for (int ni = 0; ni < 4; ni++)
#pragma unroll
            for (int k = 0; k < 4; k++) acc[mi][ni][k] = 0.0f;

#pragma unroll
    for (int j = 0; j < 2; j++) {
        CP_ASYNC16(smem0 + AHo * 2 + stoff + j * 16, Ah + gaoff + j * 8);
        CP_ASYNC16(smem0 + ALo * 2 + stoff + j * 16, Al + gaoff + j * 8);
        CP_ASYNC16(smem0 + WHo * 2 + stoff + j * 16, Wh + gwoff + j * 8);
        CP_ASYNC16(smem0 + WLo * 2 + stoff + j * 16, Wl + gwoff + j * 8);
    }
    CP_COMMIT();

    const int NK = K >> 5;
    for (int ks = 0; ks < NK; ks++) {
        CP_WAIT0();
        __syncthreads();
        if (ks + 1 < NK) {
            unsigned sB = ((ks + 1) & 1) * stageB;
            int k0 = (ks + 1) * 32;
#pragma unroll
            for (int j = 0; j < 2; j++) {
                CP_ASYNC16(smem0 + AHo * 2 + sB + stoff + j * 16, Ah + gaoff + k0 + j * 8);
                CP_ASYNC16(smem0 + ALo * 2 + sB + stoff + j * 16, Al + gaoff + k0 + j * 8);
                CP_ASYNC16(smem0 + WHo * 2 + sB + stoff + j * 16, Wh + gwoff + k0 + j * 8);
                CP_ASYNC16(smem0 + WLo * 2 + sB + stoff + j * 16, Wl + gwoff + k0 + j * 8);
            }
            CP_COMMIT();
        }
        const unsigned sB = (ks & 1) * stageB;

#pragma unroll
        for (int kc = 0; kc < 2; kc++) {
            unsigned ahf[4][4], axf[4][4];
#pragma unroll
            for (int mi = 0; mi < 4; mi++) {
                unsigned ra = ((wm + mi * 16 + laneRow + qR * 8) * SB + kc * 16 + qK * 8) * 2;
                unsigned al0, al1, al2, al3;
                ldsm4(ahf[mi][0], ahf[mi][1], ahf[mi][2], ahf[mi][3],
                      smem0 + AHo * 2 + sB + ra);
                ldsm4(al0, al1, al2, al3, smem0 + ALo * 2 + sB + ra);
                axf[mi][0] = al0; axf[mi][1] = al1;
                axf[mi][2] = ahf[mi][2]; axf[mi][3] = ahf[mi][3];
                (void)al2; (void)al3;
            }
#pragma unroll
            for (int p = 0; p < 2; p++) {
                unsigned rb = ((wn + p * 16 + laneRow + qK * 8) * SB + kc * 16 + qR * 8) * 2;
                unsigned bh[4], bl[4];
                ldsm4(bh[0], bh[1], bh[2], bh[3], smem0 + WHo * 2 + sB + rb);
                ldsm4(bl[0], bl[1], bl[2], bl[3], smem0 + WLo * 2 + sB + rb);
                unsigned bh0[2] = {bh[0], bh[1]}, bh1[2] = {bh[2], bh[3]};
                unsigned bx0[2] = {bh[0], bl[1]}, bx1[2] = {bh[2], bl[3]};
#pragma unroll
                for (int mi = 0; mi < 4; mi++) {
                    MMA_F16(acc[mi][2 * p],     ahf[mi], bh0);
                    MMA_F16(acc[mi][2 * p],     axf[mi], bx0);
                    MMA_F16(acc[mi][2 * p + 1], ahf[mi], bh1);
                    MMA_F16(acc[mi][2 * p + 1], axf[mi], bx1);
                }
            }
        }
    }

    // epilogue (fp32)
#pragma unroll
    for (int mi = 0; mi < 4; mi++)
#pragma unroll
        for (int rr = 0; rr < 2; rr++) {
            int row = bm + wm + mi * 16 + g + rr * 8;
            float* Cp = C + (size_t)row * N + bn + wn + 2 * qd;
#pragma unroll
            for (int ni = 0; ni < 4; ni++) {
                *(float2*)(Cp + ni * 8) =
                    make_float2(acc[mi][ni][2 * rr], acc[mi][ni][2 * rr + 1]);
            }
        }
}

// ---------------------------------------------------------------------------
// RoPE + split to [b,h,l,hd]; Q pre-scaled; cos/sin from table.
// ---------------------------------------------------------------------------
__global__ __launch_bounds__(256) void rope_split(const float* __restrict__ qkv)
{
    int idx = blockIdx.x * blockDim.x + threadIdx.x;
    int i = idx & 31;
    int l = (idx >> 5) & (L_ - 1);
    int h = (idx >> 16) & (H_ - 1);
    int b = idx >> 20;

    const float* row = qkv + (size_t)(b * L_ + l) * QKV_N;

    float cs = g_cs[l * 32 + i];
    float sn = g_sn[l * 32 + i];

    int off = h * HD_ + 2 * i;
    float2 qv = *(const float2*)(row + off);
    float2 kv = *(const float2*)(row + D_ + off);
    float q1 = qv.x, q2 = qv.y;
    float k1 = kv.x, k2 = kv.y;

    size_t o = ((size_t)((b * H_ + h) * L_ + l)) * HD_;
    const float qscale = 0.125f;
    float qa = (q1 * cs - q2 * sn) * qscale;
    float qb = (q1 * sn + q2 * cs) * qscale;
    float ka = k1 * cs - k2 * sn;
    float kb = k1 * sn + k2 * cs;
    float va = row[2 * D_ + h * HD_ + i];
    float vb = row[2 * D_ + h * HD_ + i + 32];

    f16 hh, ll;
    split1(qa, hh, ll); g_qh[o + i] = hh;      g_ql[o + i] = ll;
    split1(qb, hh, ll); g_qh[o + i + 32] = hh; g_ql[o + i + 32] = ll;
    split1(ka, hh, ll); g_kh[o + i] = hh;      g_kl[o + i] = ll;
    split1(kb, hh, ll); g_kh[o + i + 32] = hh; g_kl[o + i + 32] = ll;
    split1(va, hh, ll); g_vh[o + i] = hh;      g_vl[o + i] = ll;
    split1(vb, hh, ll); g_vh[o + i + 32] = hh; g_vl[o + i + 32] = ll;
}

// ---------------------------------------------------------------------------
// Flash attention, fp16 2-mma split (R14 structure; PV repack now skips
// the dead lo computation for odd P rows — hi bits identical).
// CTA = 128 queries, 8 warps x 16 q-rows, 256 threads, 2 CTAs/SM.
// ---------------------------------------------------------------------------
#define SA 72
#define QTILE (128 * SA)
#define KTILE (64 * SA)

__global__ __launch_bounds__(256, 2) void attn_h2()
{
    extern __shared__ __align__(16) f16 sma[];
    const unsigned QHo2 = 0, QLo2 = QTILE;
    const unsigned KHo2 = 2 * QTILE;
    const unsigned KLo2 = 2 * QTILE + 2 * KTILE;
    const unsigned VHo2 = 2 * QTILE + 4 * KTILE;
    const unsigned VLo2 = 2 * QTILE + 6 * KTILE;

    const int qblk = blockIdx.x, h = blockIdx.y, b = blockIdx.z;
    const int t = threadIdx.x, w = t >> 5, lane = t & 31;
    const int g = lane >> 2, qd = lane & 3;
    const int laneRow = lane & 7, qR = (lane >> 3) & 1, qK = (lane >> 4) & 1;

    const size_t base = ((size_t)(b * H_ + h)) * L_ * HD_;
    const f16* Qh = g_qh + base + (size_t)qblk * 128 * HD_;
    const f16* Ql = g_ql + base + (size_t)qblk * 128 * HD_;
    const f16* Kh = g_kh + base;
    const f16* Kl = g_kl + base;
    const f16* Vh = g_vh + base;
    const f16* Vl = g_vl + base;

    const unsigned smem0 = (unsigned)__cvta_generic_to_shared(sma);

    const int qrow = t >> 1, qhalf = t & 1;
    const unsigned qoffB = (qrow * SA) * 2 + qhalf * 64;
    const size_t qgoff = (size_t)qrow * HD_ + qhalf * 32;
    const int krow = t >> 2, kq = t & 3;
    const unsigned koffB = (krow * SA) * 2 + kq * 32;
    const size_t kgoff = (size_t)krow * HD_ + kq * 16;

#pragma unroll
    for (int j = 0; j < 4; j++) {
        CP_ASYNC16(smem0 + QHo2 * 2 + qoffB + j * 16, Qh + qgoff + j * 8);
        CP_ASYNC16(smem0 + QLo2 * 2 + qoffB + j * 16, Ql + qgoff + j * 8);
    }
#pragma unroll
    for (int j = 0; j < 2; j++) {
        CP_ASYNC16(smem0 + KHo2 * 2 + koffB + j * 16, Kh + kgoff + j * 8);
        CP_ASYNC16(smem0 + KLo2 * 2 + koffB + j * 16, Kl + kgoff + j * 8);
        CP_ASYNC16(smem0 + VHo2 * 2 + koffB + j * 16, Vh + kgoff + j * 8);
        CP_ASYNC16(smem0 + VLo2 * 2 + koffB + j * 16, Vl + kgoff + j * 8);
    }
    CP_COMMIT();

    float mrow[2] = {-3.0e38f, -3.0e38f};
    float lsum[2] = {0.0f, 0.0f};
    float oacc[8][4];
#pragma unroll
    for (int ni = 0; ni < 8; ni++)
#pragma unroll
        for (int k = 0; k < 4; k++) oacc[ni][k] = 0.0f;

    const int NKB = L_ / 64;
    for (int kb = 0; kb < NKB; kb++) {
        CP_WAIT0();
        __syncthreads();
        if (kb + 1 < NKB) {
            unsigned sB = ((kb + 1) & 1) * KTILE * 2;
            size_t go = (size_t)((kb + 1) * 64) * HD_ + kgoff;
#pragma unroll
            for (int j = 0; j < 2; j++) {
                CP_ASYNC16(smem0 + KHo2 * 2 + sB + koffB + j * 16, Kh + go + j * 8);
                CP_ASYNC16(smem0 + KLo2 * 2 + sB + koffB + j * 16, Kl + go + j * 8);
                CP_ASYNC16(smem0 + VHo2 * 2 + sB + koffB + j * 16, Vh + go + j * 8);
                CP_ASYNC16(smem0 + VLo2 * 2 + sB + koffB + j * 16, Vl + go + j * 8);
            }
            CP_COMMIT();
        }
        const unsigned sB = (kb & 1) * KTILE * 2;

        // ---- S = Q*K^T (2-mma split) ----
        float sacc[8][4];
#pragma unroll
        for (int ni = 0; ni < 8; ni++)
#pragma unroll
            for (int k = 0; k < 4; k++) sacc[ni][k] = 0.0f;

#pragma unroll
        for (int kc = 0; kc < 4; kc++) {
            unsigned qhf[4], qxf[4];
            unsigned rq = ((w * 16 + laneRow + qR * 8) * SA + kc * 16 + qK * 8) * 2;
            {
                unsigned l0, l1, l2, l3;
                ldsm4(qhf[0], qhf[1], qhf[2], qhf[3], smem0 + QHo2 * 2 + rq);
                ldsm4(l0, l1, l2, l3, smem0 + QLo2 * 2 + rq);
                qxf[0] = l0; qxf[1] = l1; qxf[2] = qhf[2]; qxf[3] = qhf[3];
                (void)l2; (void)l3;
            }
#pragma unroll
            for (int p = 0; p < 4; p++) {
                unsigned rk = ((p * 16 + laneRow + qK * 8) * SA + kc * 16 + qR * 8) * 2;
                unsigned kh[4], kl[4];
                ldsm4(kh[0], kh[1], kh[2], kh[3], smem0 + KHo2 * 2 + sB + rk);
                ldsm4(kl[0], kl[1], kl[2], kl[3], smem0 + KLo2 * 2 + sB + rk);
                unsigned kh0[2] = {kh[0], kh[1]}, kh1[2] = {kh[2], kh[3]};
                unsigned kx0[2] = {kh[0], kl[1]}, kx1[2] = {kh[2], kl[3]};
                MMA_F16(sacc[2 * p],     qhf, kh0);
                MMA_F16(sacc[2 * p],     qxf, kx0);
                MMA_F16(sacc[2 * p + 1], qhf, kh1);
                MMA_F16(sacc[2 * p + 1], qxf, kx1);
            }
        }

        // ---- online softmax ----
#pragma unroll
        for (int rr = 0; rr < 2; rr++) {
            float tm = -3.0e38f;
#pragma unroll
            for (int ni = 0; ni < 8; ni++)
                tm = fmaxf(tm, fmaxf(sacc[ni][2 * rr], sacc[ni][2 * rr + 1]));
            tm = fmaxf(tm, __shfl_xor_sync(0xffffffffu, tm, 1));
            tm = fmaxf(tm, __shfl_xor_sync(0xffffffffu, tm, 2));
            float nm = fmaxf(mrow[rr], tm);
            float sum = 0.0f;
#pragma unroll
            for (int ni = 0; ni < 8; ni++) {
                float p0 = __expf(sacc[ni][2 * rr] - nm);
                float p1 = __expf(sacc[ni][2 * rr + 1] - nm);
                sacc[ni][2 * rr] = p0;
                sacc[ni][2 * rr + 1] = p1;
                sum += p0 + p1;
            }
            sum += __shfl_xor_sync(0xffffffffu, sum, 1);
            sum += __shfl_xor_sync(0xffffffffu, sum, 2);
            float f = __expf(mrow[rr] - nm);
            lsum[rr] = lsum[rr] * f + sum;
            mrow[rr] = nm;
#pragma unroll
            for (int ni = 0; ni < 8; ni++) {
                oacc[ni][2 * rr] *= f;
                oacc[ni][2 * rr + 1] *= f;
            }
        }

        // ---- O += P*V (P from registers; odd rows hi-only — lo was dead) ----
#pragma unroll
        for (int kc = 0; kc < 4; kc++) {
            unsigned ph[4], px[4], pl0, pl1;
            split2(sacc[2 * kc][0], sacc[2 * kc][1], ph[0], pl0);
            split2(sacc[2 * kc][2], sacc[2 * kc][3], ph[1], pl1);
            ph[2] = pack2(sacc[2 * kc + 1][0], sacc[2 * kc + 1][1]);
            ph[3] = pack2(sacc[2 * kc + 1][2], sacc[2 * kc + 1][3]);
            px[0] = pl0; px[1] = pl1; px[2] = ph[2]; px[3] = ph[3];
#pragma unroll
            for (int p = 0; p < 4; p++) {
                unsigned rv = ((kc * 16 + laneRow + qR * 8) * SA + p * 16 + qK * 8) * 2;
                unsigned vh[4], vl[4];
                ldsm4t(vh[0], vh[1], vh[2], vh[3], smem0 + VHo2 * 2 + sB + rv);
                ldsm4t(vl[0], vl[1], vl[2], vl[3], smem0 + VLo2 * 2 + sB + rv);
                unsigned vh0[2] = {vh[0], vh[1]}, vh1[2] = {vh[2], vh[3]};
                unsigned vx0[2] = {vh[0], vl[1]}, vx1[2] = {vh[2], vl[3]};
                MMA_F16(oacc[2 * p],     ph, vh0);
                MMA_F16(oacc[2 * p],     px, vx0);
                MMA_F16(oacc[2 * p + 1], ph, vh1);
                MMA_F16(oacc[2 * p + 1], px, vx1);
            }
        }
    }

    // epilogue: normalize, split to fp16 hi/lo, write [b,l,d]
#pragma unroll
    for (int rr = 0; rr < 2; rr++) {
        int row = qblk * 128 + w * 16 + g + rr * 8;
        float inv = 1.0f / lsum[rr];
        unsigned* oh = (unsigned*)(g_aoh + (size_t)(b * L_ + row) * D_ + h * HD_);
        unsigned* ol = (unsigned*)(g_aol + (size_t)(b * L_ + row) * D_ + h * HD_);
#pragma unroll
        for (int ni = 0; ni < 8; ni++) {
            unsigned hv, lv;
            split2(oacc[ni][2 * rr] * inv, oacc[ni][2 * rr + 1] * inv, hv, lv);
            oh[ni * 4 + qd] = hv;
            ol[ni * 4 + qd] = lv;
        }
    }
}

// ---------------------------------------------------------------------------
// Launcher
// ---------------------------------------------------------------------------
extern "C" void kernel_launch(void* const* d_in, const int* in_sizes, int n_in,
                              void* d_out, int out_size)
{
    const float* x     = (const float*)d_in[0];
    const float* Wqkv  = (const float*)d_in[1];
    const float* Wproj = (const float*)d_in[2];
    float* out = (float*)d_out;

    float* qkv_p;
    f16 *xh, *xl, *wqh, *wql, *wph, *wpl, *aoh, *aol;
    cudaGetSymbolAddress((void**)&qkv_p, g_qkv);
    cudaGetSymbolAddress((void**)&xh,  g_xh);  cudaGetSymbolAddress((void**)&xl,  g_xl);
    cudaGetSymbolAddress((void**)&wqh, g_wqh); cudaGetSymbolAddress((void**)&wql, g_wql);
    cudaGetSymbolAddress((void**)&wph, g_wph); cudaGetSymbolAddress((void**)&wpl, g_wpl);
    cudaGetSymbolAddress((void**)&aoh, g_aoh); cudaGetSymbolAddress((void**)&aol, g_aol);

    const int smem_gemm = 8 * STG * sizeof(f16);                     // 81920
    const int smem_attn = (2 * QTILE + 8 * KTILE) * sizeof(f16);     // 110592
    cudaFuncSetAttribute(gemm_h2, cudaFuncAttributeMaxDynamicSharedMemorySize, smem_gemm);
    cudaFuncSetAttribute(attn_h2, cudaFuncAttributeMaxDynamicSharedMemorySize, smem_attn);

    // 0) rope tables + pre-split inputs to fp16 hi/lo
    rope_table<<<(L_ * 32) / 256, 256>>>();
    conv_split<<<(M_ * D_ / 4) / 256, 256>>>(x, xh, xl);
    conv_split<<<(QKV_N * D_ / 4) / 256, 256>>>(Wqkv, wqh, wql);
    conv_split<<<(D_ * D_ / 4) / 256, 256>>>(Wproj, wph, wpl);

    // 1) QKV projection (fp32 out)
    gemm_h2<<<dim3(QKV_N / 128, M_ / 128), 256, smem_gemm>>>(
        xh, xl, wqh, wql, qkv_p, M_, QKV_N, D_);

    // 2) RoPE + split to fp16 hi/lo [b,h,l,hd]
    rope_split<<<(B_ * H_ * L_ * 32) / 256, 256>>>(qkv_p);

    // 3) Attention (128-q tiles, 2 CTAs/SM)
    attn_h2<<<dim3(L_ / 128, H_, B_), 256, smem_attn>>>();

    // 4) Output projection (fp32 out)
    gemm_h2<<<dim3(D_ / 128, M_ / 128), 256, smem_gemm>>>(
        aoh, aol, wph, wpl, out, M_, D_, D_);
}